// round 4
// baseline (speedup 1.0000x reference)
#include <cuda_runtime.h>

// Problem constants (fixed shapes: B=1, C=1, H=W=96)
#define NN       9216
#define WW       96
#define INV_SXY  (1.0f / 15.0f)
#define INV_SRGB 8.0f
#define LOG2E    1.4426950408889634f
#define NHL2E    (-0.7213475204444817f)   // -0.5 * log2(e)
#define LN2      0.6931471805599453f

// Triangular tiling: 48x48 grid of 192x192 tiles -> 1176 upper-triangle blocks
// 1176 / 148 SMs = 7.95 blocks/SM -> near-perfect makespan balance,
// 2352 warps -> ~16 warps/SM resident.
#define NB      48
#define TILE    192            // NN / NB
#define NPAIR   (TILE / 2)     // 96 j-pairs per tile
#define TPB     64
#define IPT     3              // TPB * IPT == TILE
#define NBLOCKS (NB * (NB + 1) / 2)   // 1176

// ---- f32x2 helpers (sm_103a packed fp32 pipe; ptxas won't auto-fuse) ----
typedef unsigned long long u64;
__device__ __forceinline__ u64 pack2(float lo, float hi) {
    u64 r; asm("mov.b64 %0, {%1,%2};" : "=l"(r) : "f"(lo), "f"(hi)); return r;
}
__device__ __forceinline__ void unpack2(u64 v, float& lo, float& hi) {
    asm("mov.b64 {%0,%1}, %2;" : "=f"(lo), "=f"(hi) : "l"(v));
}
__device__ __forceinline__ u64 fma2(u64 a, u64 b, u64 c) {
    u64 r; asm("fma.rn.f32x2 %0, %1, %2, %3;" : "=l"(r) : "l"(a), "l"(b), "l"(c)); return r;
}
__device__ __forceinline__ u64 add2(u64 a, u64 b) {
    u64 r; asm("add.rn.f32x2 %0, %1, %2;" : "=l"(r) : "l"(a), "l"(b)); return r;
}

// Cross-block reduction state (statically zero-init; last block resets ->
// graph-replay safe and deterministic).
__device__ float        g_partial[NBLOCKS];
__device__ unsigned int g_done = 0;

// Per-pixel joint bilateral feature in log2 domain.
__device__ __forceinline__ void pixel_feat(const float* __restrict__ inp,
                                           const float* __restrict__ img, int n,
                                           float& g0, float& g1, float& g2,
                                           float& g3, float& g4,
                                           float& bb, float& ss) {
    float x = (float)(n % WW) * INV_SXY;
    float y = (float)(n / WW) * INV_SXY;
    float r = img[n]          * INV_SRGB;
    float g = img[NN + n]     * INV_SRGB;
    float b = img[2 * NN + n] * INV_SRGB;
    float sq = x * x + y * y + r * r + g * g + b * b;
    g0 = LOG2E * x;  g1 = LOG2E * y;  g2 = LOG2E * r;
    g3 = LOG2E * g;  g4 = LOG2E * b;
    bb = NHL2E * sq; ss = inp[n];
}

// Triangular-symmetric dense CRF loss with f32x2 lane-pairing over j.
//   w_ij = 2^(a_i + b_j + f_i.g_j) = exp(-0.5*d2)
// Diagonal blocks:   acc += w * (1-s_j), then * s_i
// Off-diag blocks:   acc += w * (s_i + s_j - 2 s_i s_j)   (covers both orders)
__global__ __launch_bounds__(TPB)
void crf_main_kernel(const float* __restrict__ inp,
                     const float* __restrict__ img,
                     float* __restrict__ out, int out_size) {
    // pair p: pack0={g0_0,g0_1,g1_0,g1_1} pack1={g2_0,g2_1,g3_0,g3_1}
    //         pack2={g4_0,g4_1,b_0,b_1}   pack3={t_0,t_1,s_0,s_1}
    __shared__ float4 sP0[NPAIR], sP1[NPAIR], sP2[NPAIR], sP3[NPAIR];
    __shared__ float  sred[TPB / 32];
    __shared__ int    slast;

    // Decode upper-triangle block index -> (bi, bj), bi <= bj
    int b  = blockIdx.x;
    int bi = 0;
    while (b >= NB - bi) { b -= NB - bi; bi++; }
    int bj = bi + b;

    const int t  = threadIdx.x;
    const int i0 = bi * TILE;
    const int j0 = bj * TILE;

    // Build j-tile features directly from gmem into shared (pair-packed)
    for (int p = t; p < NPAIR; p += TPB) {
        float g0a, g1a, g2a, g3a, g4a, ba, sa;
        float g0b, g1b, g2b, g3b, g4b, bb_, sb;
        pixel_feat(inp, img, j0 + 2 * p,     g0a, g1a, g2a, g3a, g4a, ba, sa);
        pixel_feat(inp, img, j0 + 2 * p + 1, g0b, g1b, g2b, g3b, g4b, bb_, sb);
        sP0[p] = make_float4(g0a, g0b, g1a, g1b);
        sP1[p] = make_float4(g2a, g2b, g3a, g3b);
        sP2[p] = make_float4(g4a, g4b, ba,  bb_);
        sP3[p] = make_float4(1.0f - sa, 1.0f - sb, sa, sb);
    }

    // Per-thread i registers, broadcast-packed (loop-invariant)
    u64 F0[IPT], F1[IPT], F2[IPT], F3[IPT], F4[IPT], A2[IPT], SI2[IPT], ACC[IPT];
    float si[IPT];
#pragma unroll
    for (int u = 0; u < IPT; u++) {
        int i = i0 + u * TPB + t;           // coalesced
        float g0, g1, g2, g3, g4, bbv, ssv;
        pixel_feat(inp, img, i, g0, g1, g2, g3, g4, bbv, ssv);
        F0[u] = pack2(LN2 * g0, LN2 * g0);
        F1[u] = pack2(LN2 * g1, LN2 * g1);
        F2[u] = pack2(LN2 * g2, LN2 * g2);
        F3[u] = pack2(LN2 * g3, LN2 * g3);
        F4[u] = pack2(LN2 * g4, LN2 * g4);
        A2[u] = pack2(bbv, bbv);
        SI2[u] = pack2(ssv, ssv);
        si[u] = ssv;
        ACC[u] = 0ull;
    }
    __syncthreads();

    const u64 NEG2 = pack2(-2.0f, -2.0f);
    const u64 ONE2 = pack2(1.0f, 1.0f);
    float tot = 0.0f;

    if (bi == bj) {
#pragma unroll 2
        for (int jj = 0; jj < NPAIR; jj++) {
            float4 P0 = sP0[jj], P1 = sP1[jj], P2 = sP2[jj], P3 = sP3[jj];
            u64 G0 = pack2(P0.x, P0.y), G1 = pack2(P0.z, P0.w);
            u64 G2 = pack2(P1.x, P1.y), G3 = pack2(P1.z, P1.w);
            u64 G4 = pack2(P2.x, P2.y), B2 = pack2(P2.z, P2.w);
            u64 T2 = pack2(P3.x, P3.y);
#pragma unroll
            for (int u = 0; u < IPT; u++) {
                u64 arg = add2(A2[u], B2);
                arg = fma2(F0[u], G0, arg);
                arg = fma2(F1[u], G1, arg);
                arg = fma2(F2[u], G2, arg);
                arg = fma2(F3[u], G3, arg);
                arg = fma2(F4[u], G4, arg);
                float a0, a1, w0, w1;
                unpack2(arg, a0, a1);
                asm("ex2.approx.ftz.f32 %0, %1;" : "=f"(w0) : "f"(a0));
                asm("ex2.approx.ftz.f32 %0, %1;" : "=f"(w1) : "f"(a1));
                ACC[u] = fma2(pack2(w0, w1), T2, ACC[u]);   // += w * (1-s_j)
            }
        }
#pragma unroll
        for (int u = 0; u < IPT; u++) {
            float lo, hi; unpack2(ACC[u], lo, hi);
            tot = fmaf(si[u], lo + hi, tot);
        }
    } else {
#pragma unroll 2
        for (int jj = 0; jj < NPAIR; jj++) {
            float4 P0 = sP0[jj], P1 = sP1[jj], P2 = sP2[jj], P3 = sP3[jj];
            u64 G0 = pack2(P0.x, P0.y), G1 = pack2(P0.z, P0.w);
            u64 G2 = pack2(P1.x, P1.y), G3 = pack2(P1.z, P1.w);
            u64 G4 = pack2(P2.x, P2.y), B2 = pack2(P2.z, P2.w);
            u64 S2 = pack2(P3.z, P3.w);
            u64 Pc = fma2(S2, NEG2, ONE2);                  // 1 - 2*s_j
#pragma unroll
            for (int u = 0; u < IPT; u++) {
                u64 arg = add2(A2[u], B2);
                arg = fma2(F0[u], G0, arg);
                arg = fma2(F1[u], G1, arg);
                arg = fma2(F2[u], G2, arg);
                arg = fma2(F3[u], G3, arg);
                arg = fma2(F4[u], G4, arg);
                float a0, a1, w0, w1;
                unpack2(arg, a0, a1);
                asm("ex2.approx.ftz.f32 %0, %1;" : "=f"(w0) : "f"(a0));
                asm("ex2.approx.ftz.f32 %0, %1;" : "=f"(w1) : "f"(a1));
                u64 C2 = fma2(SI2[u], Pc, S2);              // s_i + s_j - 2 s_i s_j
                ACC[u] = fma2(pack2(w0, w1), C2, ACC[u]);
            }
        }
#pragma unroll
        for (int u = 0; u < IPT; u++) {
            float lo, hi; unpack2(ACC[u], lo, hi);
            tot += lo + hi;                                  // both orders included
        }
    }

    // Block reduce: warp shuffle then smem (TPB = 64 -> 2 warps)
#pragma unroll
    for (int off = 16; off > 0; off >>= 1)
        tot += __shfl_xor_sync(0xFFFFFFFFu, tot, off);
    if ((t & 31) == 0) sred[t >> 5] = tot;
    __syncthreads();

    // Publish partial; last block to finish does the final (deterministic) sum.
    if (t == 0) {
        g_partial[blockIdx.x] = sred[0] + sred[1];
        __threadfence();
        unsigned int ticket = atomicAdd(&g_done, 1u);
        slast = (ticket == NBLOCKS - 1);
    }
    __syncthreads();

    if (slast) {
        __threadfence();                    // acquire all partials
        float v = 0.0f;
        for (int k = t; k < NBLOCKS; k += TPB)
            v += g_partial[k];
#pragma unroll
        for (int off = 16; off > 0; off >>= 1)
            v += __shfl_xor_sync(0xFFFFFFFFu, v, off);
        if ((t & 31) == 0) sred[t >> 5] = v;
        __syncthreads();
        if (t == 0) {
            out[0] = (sred[0] + sred[1]) * (1.0f / (float)NN);
            for (int k = 1; k < out_size; k++) out[k] = 0.0f;
            g_done = 0;                     // reset for next graph replay
        }
    }
}

extern "C" void kernel_launch(void* const* d_in, const int* in_sizes, int n_in,
                              void* d_out, int out_size) {
    const float* inp = (const float*)d_in[0];   // [1,1,96,96] seg probs
    const float* img = (const float*)d_in[1];   // [1,3,96,96] rgb
    float* out = (float*)d_out;

    crf_main_kernel<<<NBLOCKS, TPB>>>(inp, img, out, out_size);
}

// round 5
// speedup vs baseline: 1.1599x; 1.1599x over previous
#include <cuda_runtime.h>

// Problem constants (fixed shapes: B=1, C=1, H=W=96)
#define NN       9216
#define WW       96
#define INV_SXY  (1.0f / 15.0f)
#define INV_SRGB 8.0f
#define LOG2E    1.4426950408889634f
#define NHL2E    (-0.7213475204444817f)   // -0.5 * log2(e)
#define LN2      0.6931471805599453f

// Triangular tiling: 48x48 grid of 192x192 tiles -> 1176 upper-triangle blocks.
// All blocks co-resident: 1176 x 2 warps = 2352 warps ~= 16 warps/SM.
#define NB      48
#define TILE    192            // NN / NB
#define NPAIR   (TILE / 2)     // 96 j-pairs per tile
#define TPB     64
#define IPT     3              // TPB * IPT == TILE
#define NBLOCKS (NB * (NB + 1) / 2)   // 1176

// ---- f32x2 helpers (sm_103a packed fp32 pipe; ptxas won't auto-fuse) ----
typedef unsigned long long u64;
__device__ __forceinline__ u64 pack2(float lo, float hi) {
    u64 r; asm("mov.b64 %0, {%1,%2};" : "=l"(r) : "f"(lo), "f"(hi)); return r;
}
__device__ __forceinline__ void unpack2(u64 v, float& lo, float& hi) {
    asm("mov.b64 {%0,%1}, %2;" : "=f"(lo), "=f"(hi) : "l"(v));
}
__device__ __forceinline__ u64 fma2(u64 a, u64 b, u64 c) {
    u64 r; asm("fma.rn.f32x2 %0, %1, %2, %3;" : "=l"(r) : "l"(a), "l"(b), "l"(c)); return r;
}
__device__ __forceinline__ u64 add2(u64 a, u64 b) {
    u64 r; asm("add.rn.f32x2 %0, %1, %2;" : "=l"(r) : "l"(a), "l"(b)); return r;
}

// Scalar per-pixel features (for the i-side loads)
// packA = {g0, g1, g2, g3}   g = log2(e) * feat
// packB = {g4, b,  t,  s }   b = -0.5*log2(e)*|f|^2, t = 1-s
__device__ float4 g_packA[NN];
__device__ float4 g_packB[NN];
// Pair-packed j-side features: pair p covers pixels (2p, 2p+1)
// pair0 = {g0_0,g0_1, g1_0,g1_1}   pair1 = {g2_0,g2_1, g3_0,g3_1}
// pair2 = {g4_0,g4_1, b_0, b_1}    pair3 = {t_0, t_1,  s_0, s_1}
__device__ float4 g_pair0[NN / 2];
__device__ float4 g_pair1[NN / 2];
__device__ float4 g_pair2[NN / 2];
__device__ float4 g_pair3[NN / 2];

__global__ void precompute_kernel(const float* __restrict__ inp,
                                  const float* __restrict__ img,
                                  float* __restrict__ out, int out_size) {
    int p = blockIdx.x * blockDim.x + threadIdx.x;
    if (p < out_size) out[p] = 0.0f;           // fused output zeroing
    if (p >= NN / 2) return;
    float g0[2], g1[2], g2[2], g3[2], g4[2], bb[2], tt[2], ss[2];
#pragma unroll
    for (int l = 0; l < 2; l++) {
        int n = 2 * p + l;
        float x = (float)(n % WW) * INV_SXY;
        float y = (float)(n / WW) * INV_SXY;
        float r = img[n]          * INV_SRGB;
        float g = img[NN + n]     * INV_SRGB;
        float b = img[2 * NN + n] * INV_SRGB;
        float sq = x * x + y * y + r * r + g * g + b * b;
        float s = inp[n];
        g0[l] = LOG2E * x;  g1[l] = LOG2E * y;  g2[l] = LOG2E * r;
        g3[l] = LOG2E * g;  g4[l] = LOG2E * b;
        bb[l] = NHL2E * sq; tt[l] = 1.0f - s;   ss[l] = s;
        g_packA[n] = make_float4(g0[l], g1[l], g2[l], g3[l]);
        g_packB[n] = make_float4(g4[l], bb[l], tt[l], ss[l]);
    }
    g_pair0[p] = make_float4(g0[0], g0[1], g1[0], g1[1]);
    g_pair1[p] = make_float4(g2[0], g2[1], g3[0], g3[1]);
    g_pair2[p] = make_float4(g4[0], g4[1], bb[0], bb[1]);
    g_pair3[p] = make_float4(tt[0], tt[1], ss[0], ss[1]);
}

// Triangular-symmetric dense CRF loss with f32x2 lane-pairing over j.
//   w_ij = 2^(a_i + b_j + f_i.g_j) = exp(-0.5*d2)
// Diagonal blocks:   acc += w * (1-s_j), then * s_i
// Off-diag blocks:   acc += w * (s_i + s_j - 2 s_i s_j)   (covers both orders)
__global__ __launch_bounds__(TPB)
void crf_main_kernel(float* __restrict__ out) {
    __shared__ float4 sP0[NPAIR], sP1[NPAIR], sP2[NPAIR], sP3[NPAIR];
    __shared__ float  sred[TPB / 32];

    // Decode upper-triangle block index -> (bi, bj), bi <= bj
    int b  = blockIdx.x;
    int bi = 0;
    while (b >= NB - bi) { b -= NB - bi; bi++; }
    int bj = bi + b;

    const int t  = threadIdx.x;
    const int i0 = bi * TILE;
    const int p0 = bj * NPAIR;      // j-pair base

    for (int k = t; k < NPAIR; k += TPB) {
        sP0[k] = g_pair0[p0 + k];
        sP1[k] = g_pair1[p0 + k];
        sP2[k] = g_pair2[p0 + k];
        sP3[k] = g_pair3[p0 + k];
    }

    // Per-thread i registers, broadcast-packed (loop-invariant)
    u64 F0[IPT], F1[IPT], F2[IPT], F3[IPT], F4[IPT], A2[IPT], SI2[IPT], ACC[IPT];
    float si[IPT];
#pragma unroll
    for (int u = 0; u < IPT; u++) {
        int i = i0 + u * TPB + t;           // coalesced
        float4 A  = g_packA[i];
        float4 Bv = g_packB[i];
        F0[u] = pack2(LN2 * A.x,  LN2 * A.x);
        F1[u] = pack2(LN2 * A.y,  LN2 * A.y);
        F2[u] = pack2(LN2 * A.z,  LN2 * A.z);
        F3[u] = pack2(LN2 * A.w,  LN2 * A.w);
        F4[u] = pack2(LN2 * Bv.x, LN2 * Bv.x);
        A2[u] = pack2(Bv.y, Bv.y);
        SI2[u] = pack2(Bv.w, Bv.w);
        si[u] = Bv.w;
        ACC[u] = 0ull;
    }
    __syncthreads();

    const u64 NEG2 = pack2(-2.0f, -2.0f);
    const u64 ONE2 = pack2(1.0f, 1.0f);
    float tot = 0.0f;

    if (bi == bj) {
#pragma unroll 2
        for (int jj = 0; jj < NPAIR; jj++) {
            float4 P0 = sP0[jj], P1 = sP1[jj], P2 = sP2[jj], P3 = sP3[jj];
            u64 G0 = pack2(P0.x, P0.y), G1 = pack2(P0.z, P0.w);
            u64 G2 = pack2(P1.x, P1.y), G3 = pack2(P1.z, P1.w);
            u64 G4 = pack2(P2.x, P2.y), B2 = pack2(P2.z, P2.w);
            u64 T2 = pack2(P3.x, P3.y);
#pragma unroll
            for (int u = 0; u < IPT; u++) {
                u64 arg = add2(A2[u], B2);
                arg = fma2(F0[u], G0, arg);
                arg = fma2(F1[u], G1, arg);
                arg = fma2(F2[u], G2, arg);
                arg = fma2(F3[u], G3, arg);
                arg = fma2(F4[u], G4, arg);
                float a0, a1, w0, w1;
                unpack2(arg, a0, a1);
                asm("ex2.approx.ftz.f32 %0, %1;" : "=f"(w0) : "f"(a0));
                asm("ex2.approx.ftz.f32 %0, %1;" : "=f"(w1) : "f"(a1));
                ACC[u] = fma2(pack2(w0, w1), T2, ACC[u]);   // += w * (1-s_j)
            }
        }
#pragma unroll
        for (int u = 0; u < IPT; u++) {
            float lo, hi; unpack2(ACC[u], lo, hi);
            tot = fmaf(si[u], lo + hi, tot);
        }
    } else {
#pragma unroll 2
        for (int jj = 0; jj < NPAIR; jj++) {
            float4 P0 = sP0[jj], P1 = sP1[jj], P2 = sP2[jj], P3 = sP3[jj];
            u64 G0 = pack2(P0.x, P0.y), G1 = pack2(P0.z, P0.w);
            u64 G2 = pack2(P1.x, P1.y), G3 = pack2(P1.z, P1.w);
            u64 G4 = pack2(P2.x, P2.y), B2 = pack2(P2.z, P2.w);
            u64 S2 = pack2(P3.z, P3.w);
            u64 Pc = fma2(S2, NEG2, ONE2);                  // 1 - 2*s_j
#pragma unroll
            for (int u = 0; u < IPT; u++) {
                u64 arg = add2(A2[u], B2);
                arg = fma2(F0[u], G0, arg);
                arg = fma2(F1[u], G1, arg);
                arg = fma2(F2[u], G2, arg);
                arg = fma2(F3[u], G3, arg);
                arg = fma2(F4[u], G4, arg);
                float a0, a1, w0, w1;
                unpack2(arg, a0, a1);
                asm("ex2.approx.ftz.f32 %0, %1;" : "=f"(w0) : "f"(a0));
                asm("ex2.approx.ftz.f32 %0, %1;" : "=f"(w1) : "f"(a1));
                u64 C2 = fma2(SI2[u], Pc, S2);              // s_i + s_j - 2 s_i s_j
                ACC[u] = fma2(pack2(w0, w1), C2, ACC[u]);
            }
        }
#pragma unroll
        for (int u = 0; u < IPT; u++) {
            float lo, hi; unpack2(ACC[u], lo, hi);
            tot += lo + hi;                                  // both orders included
        }
    }

    tot *= (1.0f / (float)NN);

    // Block reduce: warp shuffle then smem (TPB = 64 -> 2 warps)
#pragma unroll
    for (int off = 16; off > 0; off >>= 1)
        tot += __shfl_xor_sync(0xFFFFFFFFu, tot, off);
    if ((t & 31) == 0) sred[t >> 5] = tot;
    __syncthreads();
    if (t == 0) atomicAdd(out, sred[0] + sred[1]);
}

extern "C" void kernel_launch(void* const* d_in, const int* in_sizes, int n_in,
                              void* d_out, int out_size) {
    const float* inp = (const float*)d_in[0];   // [1,1,96,96] seg probs
    const float* img = (const float*)d_in[1];   // [1,3,96,96] rgb
    float* out = (float*)d_out;

    precompute_kernel<<<(NN / 2 + 255) / 256, 256>>>(inp, img, out, out_size);
    crf_main_kernel<<<NBLOCKS, TPB>>>(out);
}